// round 8
// baseline (speedup 1.0000x reference)
#include <cuda_runtime.h>
#include <math.h>

// Depthwise 3D Gaussian blur (xi=2, K=13, pad=6) on (1,3,192,192,192) fp32.
// R7: WH kernel v2 — W-blur staged once into smem (no recompute), 192-thread
//     CTAs, 48.4 KB smem -> 24 warps/SM. D pass split into 8 segments.

#define NN 192
#define RR 6
#define KK 13

#define WT   48     // w-tile (12 float4)
#define HT   96     // h outputs per CTA
#define RAWR 108    // raw rows incl +-6 h halo
#define RSTR 60     // raw row stride in floats (48 + 12 w halo)
#define BSTR 52     // blur1 row stride in floats (48 data + 4 pad)

constexpr int PLANE = NN * NN;          // 36864
constexpr int VOL   = NN * NN * NN;     // 7077888
constexpr long TOTAL = 3L * VOL;

// Scratch (allocation-free rule): one 85 MB temp.
__device__ __align__(16) float g_tmpA[TOTAL];

struct GW { float g[KK]; };

// Packed fp32x2 FMA (Blackwell f32x2 pipe).
__device__ __forceinline__ float2 ffma2(float2 a, float2 b, float2 c) {
    float2 r;
    asm("fma.rn.f32x2 %0, %1, %2, %3;"
        : "=l"(reinterpret_cast<unsigned long long&>(r))
        : "l"(reinterpret_cast<unsigned long long&>(a)),
          "l"(reinterpret_cast<unsigned long long&>(b)),
          "l"(reinterpret_cast<unsigned long long&>(c)));
    return r;
}

// ---------------- Kernel 1: fused W + H blur ------------------------------
// grid = (4 wchunks, 192 d, 3c x 2 hchunk), block = 192 threads.
// Stage A: W-blur raw rows once into blur1 (smem). Stage B: 13-row register
// sliding window over blur1 along h. smem total = 25,920 + 22,464 = 48,384 B.
__global__ __launch_bounds__(192, 4) void conv_wh_kernel(const float* __restrict__ in,
                                                         float* __restrict__ out, GW gw) {
    __shared__ __align__(16) float raw[RAWR * RSTR];    // 25,920 B
    __shared__ __align__(16) float blur1[RAWR * BSTR];  // 22,464 B

    const int c  = blockIdx.z >> 1;
    const int hc = blockIdx.z & 1;
    const int d  = blockIdx.y;
    const int w0 = blockIdx.x * WT;
    const int h0 = hc * HT;
    const int tid = threadIdx.x;

    const float* src = in + (c * NN + d) * PLANE;

    // ---- load raw tile: rows h0-6..h0+101, cols w0-6..w0+53 (zeros outside)
    for (int idx = tid; idx < RAWR * 30; idx += 192) {
        const int h = idx / 30;
        const int k = idx - h * 30;
        const int gh = h0 + h - RR;
        const int gwp = w0 - RR + 2 * k;
        float2 v = make_float2(0.f, 0.f);
        if ((unsigned)gh < NN && (unsigned)gwp < NN)
            v = *(const float2*)(src + gh * NN + gwp);
        *(float2*)(raw + h * RSTR + 2 * k) = v;
    }
    __syncthreads();

    // ---- stage A: W-blur each raw row once -> blur1 (1296 float4 tasks) ---
    for (int t = tid; t < RAWR * 12; t += 192) {
        const int row = t / 12;
        const int tw  = t - row * 12;
        const float* rp = raw + row * RSTR + 4 * tw;
        const float4 x0 = *(const float4*)(rp);
        const float4 x1 = *(const float4*)(rp + 4);
        const float4 x2 = *(const float4*)(rp + 8);
        const float4 x3 = *(const float4*)(rp + 12);
        const float rr[16] = {x0.x, x0.y, x0.z, x0.w, x1.x, x1.y, x1.z, x1.w,
                              x2.x, x2.y, x2.z, x2.w, x3.x, x3.y, x3.z, x3.w};
        float o0 = 0.f, o1 = 0.f, o2 = 0.f, o3 = 0.f;
#pragma unroll
        for (int j = 0; j < KK; j++) {
            const float gj = gw.g[j];
            o0 = fmaf(gj, rr[j],     o0);
            o1 = fmaf(gj, rr[j + 1], o1);
            o2 = fmaf(gj, rr[j + 2], o2);
            o3 = fmaf(gj, rr[j + 3], o3);
        }
        *(float4*)(blur1 + row * BSTR + 4 * tw) = make_float4(o0, o1, o2, o3);
    }
    __syncthreads();

    // ---- stage B: H-blur with 13-deep register window over blur1 ----------
    const int tw = tid % 12;        // float4 slot in w
    const int hg = tid / 12;        // 0..15
    const int hb = hg * 6;          // local output row base (HSEG = 6)

    const float* s2 = blur1 + hb * BSTR + 4 * tw;   // row hb (= window start)
    float* dst = out + (c * NN + d) * PLANE + (h0 + hb) * NN + w0 + 4 * tw;

    float2 a[KK], b[KK];
#pragma unroll
    for (int j = 0; j < KK - 1; j++) {
        const float4 v = *(const float4*)(s2 + j * BSTR);
        a[j] = make_float2(v.x, v.y);
        b[j] = make_float2(v.z, v.w);
    }

#pragma unroll
    for (int i = 0; i < 6; i++) {
        const float4 v = *(const float4*)(s2 + (i + 12) * BSTR);
        a[KK - 1] = make_float2(v.x, v.y);
        b[KK - 1] = make_float2(v.z, v.w);

        float2 acc0 = make_float2(0.f, 0.f);
        float2 acc1 = make_float2(0.f, 0.f);
#pragma unroll
        for (int j = 0; j < KK; j++) {
            const float2 gj = make_float2(gw.g[j], gw.g[j]);
            acc0 = ffma2(gj, a[j], acc0);
            acc1 = ffma2(gj, b[j], acc1);
        }
        *(float4*)(dst + i * NN) = make_float4(acc0.x, acc0.y, acc1.x, acc1.y);

#pragma unroll
        for (int j = 0; j < KK - 1; j++) { a[j] = a[j + 1]; b[j] = b[j + 1]; }
    }
}

// ---------------- Kernel 2: conv along D (strided axis) --------------------
// float4 across W (threadIdx.x = 0..47), sliding 13-wide register window
// along d; axis split into 8 segments of 24. Strides in float4 units.
__global__ void conv_axis_kernel(const float4* __restrict__ in, float4* __restrict__ out,
                                 GW gw, int cnt_lo, int s_lo, int s_hi, int stride) {
    const int o = blockIdx.y * blockDim.y + threadIdx.y;   // c*192 + h, < 576
    const int base = (o / cnt_lo) * s_hi + (o % cnt_lo) * s_lo;
    const float4* pin = in + base + threadIdx.x;
    float4* pout = out + base + threadIdx.x;

    const int p0 = blockIdx.x * 24;

    float2 w0[KK], w1[KK];
    const float2 z2 = make_float2(0.f, 0.f);

#pragma unroll
    for (int j = 0; j < KK - 1; j++) {
        int q = p0 - RR + j;
        float2 aa = z2, bb = z2;
        if (q >= 0 && q < NN) {
            float4 v = pin[q * stride];
            aa = make_float2(v.x, v.y);
            bb = make_float2(v.z, v.w);
        }
        w0[j] = aa; w1[j] = bb;
    }

#pragma unroll
    for (int i = 0; i < 24; i++) {
        const int p = p0 + i;
        const int q = p + RR;
        float2 aa = z2, bb = z2;
        if (q < NN) {
            float4 v = pin[q * stride];
            aa = make_float2(v.x, v.y);
            bb = make_float2(v.z, v.w);
        }
        w0[KK - 1] = aa; w1[KK - 1] = bb;

        float2 acc0 = z2, acc1 = z2;
#pragma unroll
        for (int j = 0; j < KK; j++) {
            const float2 gj = make_float2(gw.g[j], gw.g[j]);
            acc0 = ffma2(gj, w0[j], acc0);
            acc1 = ffma2(gj, w1[j], acc1);
        }
        pout[p * stride] = make_float4(acc0.x, acc0.y, acc1.x, acc1.y);

#pragma unroll
        for (int j = 0; j < KK - 1; j++) { w0[j] = w0[j + 1]; w1[j] = w1[j + 1]; }
    }
}

extern "C" void kernel_launch(void* const* d_in, const int* in_sizes, int n_in,
                              void* d_out, int out_size) {
    const float* x = (const float*)d_in[0];   // (1,3,192,192,192) fp32
    float* out = (float*)d_out;

    void* pA = nullptr;
    cudaGetSymbolAddress(&pA, g_tmpA);
    float* tA = (float*)pA;

    // Host-side weights (double precision, normalized Gaussian, xi=2).
    GW gw;
    {
        double v[KK], s = 0.0;
        for (int j = 0; j < KK; j++) {
            double dd = (double)(j - RR);
            v[j] = exp(-dd * dd / 8.0);
            s += v[j];
        }
        for (int j = 0; j < KK; j++) gw.g[j] = (float)(v[j] / s);
    }

    // Fused W+H blur: x -> tA. grid z = 3c x 2 hchunks.
    conv_wh_kernel<<<dim3(NN / WT, NN, 6), 192>>>(x, tA, gw);

    // D pass: tA -> out. outer o = c*192 + h; stride along d = 9216 float4.
    conv_axis_kernel<<<dim3(8, 576 / 4), dim3(48, 4)>>>(
        (const float4*)tA, (float4*)out, gw,
        /*cnt_lo=*/NN, /*s_lo=*/NN / 4, /*s_hi=*/VOL / 4, /*stride=*/PLANE / 4);
}

// round 10
// speedup vs baseline: 1.3404x; 1.3404x over previous
#include <cuda_runtime.h>
#include <math.h>

// Depthwise 3D Gaussian blur (xi=2, K=13, pad=6) on (1,3,192,192,192) fp32.
// R9: R8 with the tile-loader coverage bug fixed (flattened idx loop — the
//     phase-partitioned loader left cols 12..29 of every 7th row unwritten).
//     Staged WH kernel (W-blur once into smem), unclamped regs; D pass 4 seg.

#define NN 192
#define RR 6
#define KK 13

#define WT   48     // w-tile (12 float4)
#define HT   96     // h outputs per CTA
#define RAWR 108    // raw rows incl +-6 h halo
#define RSTR 60     // raw row stride in floats (48 + 12 w halo)
#define BSTR 52     // blur1 row stride in floats (48 data + 4 pad)

constexpr int PLANE = NN * NN;          // 36864
constexpr int VOL   = NN * NN * NN;     // 7077888
constexpr long TOTAL = 3L * VOL;

// Scratch (allocation-free rule): one 85 MB temp.
__device__ __align__(16) float g_tmpA[TOTAL];

struct GW { float g[KK]; };

// Packed fp32x2 FMA (Blackwell f32x2 pipe).
__device__ __forceinline__ float2 ffma2(float2 a, float2 b, float2 c) {
    float2 r;
    asm("fma.rn.f32x2 %0, %1, %2, %3;"
        : "=l"(reinterpret_cast<unsigned long long&>(r))
        : "l"(reinterpret_cast<unsigned long long&>(a)),
          "l"(reinterpret_cast<unsigned long long&>(b)),
          "l"(reinterpret_cast<unsigned long long&>(c)));
    return r;
}

// ---------------- Kernel 1: fused W + H blur ------------------------------
// grid = (4 wchunks, 192 d, 3c x 2 hchunk), block = 192 threads.
// Stage A: W-blur each raw row ONCE into blur1 (smem). Stage B: 13-row
// register sliding window over blur1 along h, packed f32x2 accumulate.
// smem = 25,920 + 22,464 = 48,384 B -> 4 CTAs/SM, 24 warps/SM.
__global__ __launch_bounds__(192) void conv_wh_kernel(const float* __restrict__ in,
                                                      float* __restrict__ out, GW gw) {
    __shared__ __align__(16) float raw[RAWR * RSTR];    // 25,920 B
    __shared__ __align__(16) float blur1[RAWR * BSTR];  // 22,464 B

    const int c  = blockIdx.z >> 1;
    const int hc = blockIdx.z & 1;
    const int d  = blockIdx.y;
    const int w0 = blockIdx.x * WT;
    const int h0 = hc * HT;
    const int tid = threadIdx.x;

    const float* src = in + (c * NN + d) * PLANE;

    // ---- load raw tile: rows h0-6..h0+101, cols w0-6..w0+53 (zeros outside)
    // 108 rows x 30 float2, flattened (full coverage: 3240 tasks / 192 thr).
    for (int idx = tid; idx < RAWR * 30; idx += 192) {
        const int h = idx / 30;
        const int k = idx - h * 30;
        const int gh = h0 + h - RR;
        const int gwp = w0 - RR + 2 * k;
        float2 v = make_float2(0.f, 0.f);
        if ((unsigned)gh < NN && (unsigned)gwp < NN)
            v = *(const float2*)(src + gh * NN + gwp);
        *(float2*)(raw + h * RSTR + 2 * k) = v;
    }
    __syncthreads();

    // ---- stage A: W-blur each raw row once -> blur1 (1296 float4 tasks) ---
    for (int t = tid; t < RAWR * 12; t += 192) {
        const int row = t / 12;
        const int tw  = t - row * 12;
        const float* rp = raw + row * RSTR + 4 * tw;
        const float4 x0 = *(const float4*)(rp);
        const float4 x1 = *(const float4*)(rp + 4);
        const float4 x2 = *(const float4*)(rp + 8);
        const float4 x3 = *(const float4*)(rp + 12);
        const float rr[16] = {x0.x, x0.y, x0.z, x0.w, x1.x, x1.y, x1.z, x1.w,
                              x2.x, x2.y, x2.z, x2.w, x3.x, x3.y, x3.z, x3.w};
        float o0 = 0.f, o1 = 0.f, o2 = 0.f, o3 = 0.f;
#pragma unroll
        for (int j = 0; j < KK; j++) {
            const float gj = gw.g[j];
            o0 = fmaf(gj, rr[j],     o0);
            o1 = fmaf(gj, rr[j + 1], o1);
            o2 = fmaf(gj, rr[j + 2], o2);
            o3 = fmaf(gj, rr[j + 3], o3);
        }
        *(float4*)(blur1 + row * BSTR + 4 * tw) = make_float4(o0, o1, o2, o3);
    }
    __syncthreads();

    // ---- stage B: H-blur with 13-deep float4 register window over blur1 ---
    const int tw = tid % 12;        // float4 slot in w
    const int hg = tid / 12;        // 0..15
    const int hb = hg * 6;          // local output row base (6 outputs/thread)

    const float* s2 = blur1 + hb * BSTR + 4 * tw;
    float* dst = out + (c * NN + d) * PLANE + (h0 + hb) * NN + w0 + 4 * tw;

    float4 win[KK];
#pragma unroll
    for (int j = 0; j < KK - 1; j++)
        win[j] = *(const float4*)(s2 + j * BSTR);

#pragma unroll
    for (int i = 0; i < 6; i++) {
        win[KK - 1] = *(const float4*)(s2 + (i + 12) * BSTR);

        float2 acc0 = make_float2(0.f, 0.f);
        float2 acc1 = make_float2(0.f, 0.f);
#pragma unroll
        for (int j = 0; j < KK; j++) {
            const float2 gj = make_float2(gw.g[j], gw.g[j]);
            acc0 = ffma2(gj, make_float2(win[j].x, win[j].y), acc0);
            acc1 = ffma2(gj, make_float2(win[j].z, win[j].w), acc1);
        }
        *(float4*)(dst + i * NN) = make_float4(acc0.x, acc0.y, acc1.x, acc1.y);

#pragma unroll
        for (int j = 0; j < KK - 1; j++) win[j] = win[j + 1];
    }
}

// ---------------- Kernel 2: conv along D (strided axis) --------------------
// float4 across W (threadIdx.x = 0..47), sliding 13-wide register window
// along d; axis split into 4 segments of 48 (best measured config).
// (48,2)-thread blocks for wave balance. Strides in float4 units.
__global__ void conv_axis_kernel(const float4* __restrict__ in, float4* __restrict__ out,
                                 GW gw, int cnt_lo, int s_lo, int s_hi, int stride) {
    const int o = blockIdx.y * blockDim.y + threadIdx.y;   // c*192 + h, < 576
    const int base = (o / cnt_lo) * s_hi + (o % cnt_lo) * s_lo;
    const float4* pin = in + base + threadIdx.x;
    float4* pout = out + base + threadIdx.x;

    const int p0 = blockIdx.x * 48;

    float2 w0[KK], w1[KK];
    const float2 z2 = make_float2(0.f, 0.f);

#pragma unroll
    for (int j = 0; j < KK - 1; j++) {
        int q = p0 - RR + j;
        float2 aa = z2, bb = z2;
        if (q >= 0 && q < NN) {
            float4 v = pin[q * stride];
            aa = make_float2(v.x, v.y);
            bb = make_float2(v.z, v.w);
        }
        w0[j] = aa; w1[j] = bb;
    }

#pragma unroll
    for (int i = 0; i < 48; i++) {
        const int p = p0 + i;
        const int q = p + RR;
        float2 aa = z2, bb = z2;
        if (q < NN) {
            float4 v = pin[q * stride];
            aa = make_float2(v.x, v.y);
            bb = make_float2(v.z, v.w);
        }
        w0[KK - 1] = aa; w1[KK - 1] = bb;

        float2 acc0 = z2, acc1 = z2;
#pragma unroll
        for (int j = 0; j < KK; j++) {
            const float2 gj = make_float2(gw.g[j], gw.g[j]);
            acc0 = ffma2(gj, w0[j], acc0);
            acc1 = ffma2(gj, w1[j], acc1);
        }
        pout[p * stride] = make_float4(acc0.x, acc0.y, acc1.x, acc1.y);

#pragma unroll
        for (int j = 0; j < KK - 1; j++) { w0[j] = w0[j + 1]; w1[j] = w1[j + 1]; }
    }
}

extern "C" void kernel_launch(void* const* d_in, const int* in_sizes, int n_in,
                              void* d_out, int out_size) {
    const float* x = (const float*)d_in[0];   // (1,3,192,192,192) fp32
    float* out = (float*)d_out;

    void* pA = nullptr;
    cudaGetSymbolAddress(&pA, g_tmpA);
    float* tA = (float*)pA;

    // Host-side weights (double precision, normalized Gaussian, xi=2).
    GW gw;
    {
        double v[KK], s = 0.0;
        for (int j = 0; j < KK; j++) {
            double dd = (double)(j - RR);
            v[j] = exp(-dd * dd / 8.0);
            s += v[j];
        }
        for (int j = 0; j < KK; j++) gw.g[j] = (float)(v[j] / s);
    }

    // Fused W+H blur: x -> tA. grid z = 3c x 2 hchunks. 2304 CTAs.
    conv_wh_kernel<<<dim3(NN / WT, NN, 6), 192>>>(x, tA, gw);

    // D pass: tA -> out. 4 segments x 288 blocks of (48,2). 1152 CTAs.
    conv_axis_kernel<<<dim3(4, 576 / 2), dim3(48, 2)>>>(
        (const float4*)tA, (float4*)out, gw,
        /*cnt_lo=*/NN, /*s_lo=*/NN / 4, /*s_hi=*/VOL / 4, /*stride=*/PLANE / 4);
}

// round 11
// speedup vs baseline: 1.8338x; 1.3680x over previous
#include <cuda_runtime.h>
#include <math.h>

// Depthwise 3D Gaussian blur (xi=2, K=13, pad=6) on (1,3,192,192,192) fp32.
// R10: R6-style single-stage WH kernel (W-blur recompute in sliding window),
//      but with half-height tile (108x60 = 25.9 KB smem) -> ~8 CTAs/SM,
//      24 warps/SM. D pass: best measured config (4 seg, (48,4), grid 576).

#define NN 192
#define RR 6
#define KK 13

#define WT   48     // w-tile (12 float4)
#define HT   96     // h outputs per CTA
#define RAWR 108    // raw rows incl +-6 h halo
#define RSTR 60     // raw row stride in floats (48 + 12 w halo)
#define HSEG 12     // h outputs per thread (8 h-groups)

constexpr int PLANE = NN * NN;          // 36864
constexpr int VOL   = NN * NN * NN;     // 7077888
constexpr long TOTAL = 3L * VOL;

// Scratch (allocation-free rule): one 85 MB temp.
__device__ __align__(16) float g_tmpA[TOTAL];

struct GW { float g[KK]; };

// Packed fp32x2 FMA (Blackwell f32x2 pipe).
__device__ __forceinline__ float2 ffma2(float2 a, float2 b, float2 c) {
    float2 r;
    asm("fma.rn.f32x2 %0, %1, %2, %3;"
        : "=l"(reinterpret_cast<unsigned long long&>(r))
        : "l"(reinterpret_cast<unsigned long long&>(a)),
          "l"(reinterpret_cast<unsigned long long&>(b)),
          "l"(reinterpret_cast<unsigned long long&>(c)));
    return r;
}

// ---------------- Kernel 1: fused W + H blur ------------------------------
// grid = (4 wchunks, 192 d, 3c x 2 hchunks), block = 96 threads (12 tw x 8 hg).
// Raw tile in smem; each thread W-blurs rows on the fly while sliding a
// 13-deep register window along h (recompute amp 2.0, FMA non-binding).
__global__ __launch_bounds__(96) void conv_wh_kernel(const float* __restrict__ in,
                                                     float* __restrict__ out, GW gw) {
    __shared__ __align__(16) float raw[RAWR * RSTR];    // 25,920 B

    const int c  = blockIdx.z >> 1;
    const int hc = blockIdx.z & 1;
    const int d  = blockIdx.y;
    const int w0 = blockIdx.x * WT;
    const int h0 = hc * HT;
    const int tid = threadIdx.x;

    const float* src = in + (c * NN + d) * PLANE;

    // ---- load raw tile: rows h0-6..h0+101, cols w0-6..w0+53 (zeros outside)
    // 108 rows x 30 float2, flattened (full coverage).
    for (int idx = tid; idx < RAWR * 30; idx += 96) {
        const int h = idx / 30;
        const int k = idx - h * 30;
        const int gh = h0 + h - RR;
        const int gwp = w0 - RR + 2 * k;
        float2 v = make_float2(0.f, 0.f);
        if ((unsigned)gh < NN && (unsigned)gwp < NN)
            v = *(const float2*)(src + gh * NN + gwp);
        *(float2*)(raw + h * RSTR + 2 * k) = v;
    }
    __syncthreads();

    const int tw = tid % 12;        // float4 slot in w
    const int hg = tid / 12;        // 0..7
    const int hb = hg * HSEG;       // local output row base

    float* dst = out + (c * NN + d) * PLANE + (h0 + hb) * NN + w0 + 4 * tw;

    // W-blur of local raw row r at float4 slot tw -> float4
    auto wblur = [&](int r) -> float4 {
        const float* rp = raw + r * RSTR + 4 * tw;
        const float4 x0 = *(const float4*)(rp);
        const float4 x1 = *(const float4*)(rp + 4);
        const float4 x2 = *(const float4*)(rp + 8);
        const float4 x3 = *(const float4*)(rp + 12);
        const float rr[16] = {x0.x, x0.y, x0.z, x0.w, x1.x, x1.y, x1.z, x1.w,
                              x2.x, x2.y, x2.z, x2.w, x3.x, x3.y, x3.z, x3.w};
        float o0 = 0.f, o1 = 0.f, o2 = 0.f, o3 = 0.f;
#pragma unroll
        for (int j = 0; j < KK; j++) {
            const float gj = gw.g[j];
            o0 = fmaf(gj, rr[j],     o0);
            o1 = fmaf(gj, rr[j + 1], o1);
            o2 = fmaf(gj, rr[j + 2], o2);
            o3 = fmaf(gj, rr[j + 3], o3);
        }
        return make_float4(o0, o1, o2, o3);
    };

    // 13-deep sliding window of W-blurred rows (output row o needs raw rows
    // o..o+12 local; thread covers raw rows hb..hb+23 <= 107).
    float4 win[KK];
#pragma unroll
    for (int j = 0; j < KK - 1; j++) win[j] = wblur(hb + j);

#pragma unroll
    for (int i = 0; i < HSEG; i++) {
        win[KK - 1] = wblur(hb + i + (KK - 1));

        float2 acc0 = make_float2(0.f, 0.f);
        float2 acc1 = make_float2(0.f, 0.f);
#pragma unroll
        for (int j = 0; j < KK; j++) {
            const float2 gj = make_float2(gw.g[j], gw.g[j]);
            acc0 = ffma2(gj, make_float2(win[j].x, win[j].y), acc0);
            acc1 = ffma2(gj, make_float2(win[j].z, win[j].w), acc1);
        }
        *(float4*)(dst + i * NN) = make_float4(acc0.x, acc0.y, acc1.x, acc1.y);

#pragma unroll
        for (int j = 0; j < KK - 1; j++) win[j] = win[j + 1];
    }
}

// ---------------- Kernel 2: conv along D (strided axis) --------------------
// float4 across W (threadIdx.x = 0..47), sliding 13-wide register window
// along d; 4 segments of 48 (best measured). Strides in float4 units.
__global__ void conv_axis_kernel(const float4* __restrict__ in, float4* __restrict__ out,
                                 GW gw, int cnt_lo, int s_lo, int s_hi, int stride) {
    const int o = blockIdx.y * blockDim.y + threadIdx.y;   // c*192 + h, < 576
    const int base = (o / cnt_lo) * s_hi + (o % cnt_lo) * s_lo;
    const float4* pin = in + base + threadIdx.x;
    float4* pout = out + base + threadIdx.x;

    const int p0 = blockIdx.x * 48;

    float2 w0[KK], w1[KK];
    const float2 z2 = make_float2(0.f, 0.f);

#pragma unroll
    for (int j = 0; j < KK - 1; j++) {
        int q = p0 - RR + j;
        float2 aa = z2, bb = z2;
        if (q >= 0 && q < NN) {
            float4 v = pin[q * stride];
            aa = make_float2(v.x, v.y);
            bb = make_float2(v.z, v.w);
        }
        w0[j] = aa; w1[j] = bb;
    }

#pragma unroll
    for (int i = 0; i < 48; i++) {
        const int p = p0 + i;
        const int q = p + RR;
        float2 aa = z2, bb = z2;
        if (q < NN) {
            float4 v = pin[q * stride];
            aa = make_float2(v.x, v.y);
            bb = make_float2(v.z, v.w);
        }
        w0[KK - 1] = aa; w1[KK - 1] = bb;

        float2 acc0 = z2, acc1 = z2;
#pragma unroll
        for (int j = 0; j < KK; j++) {
            const float2 gj = make_float2(gw.g[j], gw.g[j]);
            acc0 = ffma2(gj, w0[j], acc0);
            acc1 = ffma2(gj, w1[j], acc1);
        }
        pout[p * stride] = make_float4(acc0.x, acc0.y, acc1.x, acc1.y);

#pragma unroll
        for (int j = 0; j < KK - 1; j++) { w0[j] = w0[j + 1]; w1[j] = w1[j + 1]; }
    }
}

extern "C" void kernel_launch(void* const* d_in, const int* in_sizes, int n_in,
                              void* d_out, int out_size) {
    const float* x = (const float*)d_in[0];   // (1,3,192,192,192) fp32
    float* out = (float*)d_out;

    void* pA = nullptr;
    cudaGetSymbolAddress(&pA, g_tmpA);
    float* tA = (float*)pA;

    // Host-side weights (double precision, normalized Gaussian, xi=2).
    GW gw;
    {
        double v[KK], s = 0.0;
        for (int j = 0; j < KK; j++) {
            double dd = (double)(j - RR);
            v[j] = exp(-dd * dd / 8.0);
            s += v[j];
        }
        for (int j = 0; j < KK; j++) gw.g[j] = (float)(v[j] / s);
    }

    // Fused W+H blur: x -> tA. 4608 CTAs of 96 threads.
    conv_wh_kernel<<<dim3(NN / WT, NN, 6), 96>>>(x, tA, gw);

    // D pass: tA -> out. 4 segments x 144 blocks of (48,4). 576 CTAs.
    conv_axis_kernel<<<dim3(4, 576 / 4), dim3(48, 4)>>>(
        (const float4*)tA, (float4*)out, gw,
        /*cnt_lo=*/NN, /*s_lo=*/NN / 4, /*s_hi=*/VOL / 4, /*stride=*/PLANE / 4);
}

// round 12
// speedup vs baseline: 1.9801x; 1.0798x over previous
#include <cuda_runtime.h>
#include <math.h>

// Depthwise 3D Gaussian blur (xi=2, K=13, pad=6) on (1,3,192,192,192) fp32.
// R11: WH kernel unchanged from R10 (best measured). D pass reworked to
//      float2-per-thread: window 26 regs -> ~42 warps/SM (2x occupancy),
//      doubling outstanding loads at identical traffic.

#define NN 192
#define RR 6
#define KK 13

#define WT   48     // w-tile (12 float4)
#define HT   96     // h outputs per CTA
#define RAWR 108    // raw rows incl +-6 h halo
#define RSTR 60     // raw row stride in floats (48 + 12 w halo)
#define HSEG 12     // h outputs per thread (8 h-groups)

constexpr int PLANE = NN * NN;          // 36864
constexpr int VOL   = NN * NN * NN;     // 7077888
constexpr long TOTAL = 3L * VOL;

// Scratch (allocation-free rule): one 85 MB temp.
__device__ __align__(16) float g_tmpA[TOTAL];

struct GW { float g[KK]; };

// Packed fp32x2 FMA (Blackwell f32x2 pipe).
__device__ __forceinline__ float2 ffma2(float2 a, float2 b, float2 c) {
    float2 r;
    asm("fma.rn.f32x2 %0, %1, %2, %3;"
        : "=l"(reinterpret_cast<unsigned long long&>(r))
        : "l"(reinterpret_cast<unsigned long long&>(a)),
          "l"(reinterpret_cast<unsigned long long&>(b)),
          "l"(reinterpret_cast<unsigned long long&>(c)));
    return r;
}

// ---------------- Kernel 1: fused W + H blur (R10, best measured) ----------
// grid = (4 wchunks, 192 d, 3c x 2 hchunks), block = 96 threads (12 tw x 8 hg).
__global__ __launch_bounds__(96) void conv_wh_kernel(const float* __restrict__ in,
                                                     float* __restrict__ out, GW gw) {
    __shared__ __align__(16) float raw[RAWR * RSTR];    // 25,920 B

    const int c  = blockIdx.z >> 1;
    const int hc = blockIdx.z & 1;
    const int d  = blockIdx.y;
    const int w0 = blockIdx.x * WT;
    const int h0 = hc * HT;
    const int tid = threadIdx.x;

    const float* src = in + (c * NN + d) * PLANE;

    for (int idx = tid; idx < RAWR * 30; idx += 96) {
        const int h = idx / 30;
        const int k = idx - h * 30;
        const int gh = h0 + h - RR;
        const int gwp = w0 - RR + 2 * k;
        float2 v = make_float2(0.f, 0.f);
        if ((unsigned)gh < NN && (unsigned)gwp < NN)
            v = *(const float2*)(src + gh * NN + gwp);
        *(float2*)(raw + h * RSTR + 2 * k) = v;
    }
    __syncthreads();

    const int tw = tid % 12;        // float4 slot in w
    const int hg = tid / 12;        // 0..7
    const int hb = hg * HSEG;       // local output row base

    float* dst = out + (c * NN + d) * PLANE + (h0 + hb) * NN + w0 + 4 * tw;

    auto wblur = [&](int r) -> float4 {
        const float* rp = raw + r * RSTR + 4 * tw;
        const float4 x0 = *(const float4*)(rp);
        const float4 x1 = *(const float4*)(rp + 4);
        const float4 x2 = *(const float4*)(rp + 8);
        const float4 x3 = *(const float4*)(rp + 12);
        const float rr[16] = {x0.x, x0.y, x0.z, x0.w, x1.x, x1.y, x1.z, x1.w,
                              x2.x, x2.y, x2.z, x2.w, x3.x, x3.y, x3.z, x3.w};
        float o0 = 0.f, o1 = 0.f, o2 = 0.f, o3 = 0.f;
#pragma unroll
        for (int j = 0; j < KK; j++) {
            const float gj = gw.g[j];
            o0 = fmaf(gj, rr[j],     o0);
            o1 = fmaf(gj, rr[j + 1], o1);
            o2 = fmaf(gj, rr[j + 2], o2);
            o3 = fmaf(gj, rr[j + 3], o3);
        }
        return make_float4(o0, o1, o2, o3);
    };

    float4 win[KK];
#pragma unroll
    for (int j = 0; j < KK - 1; j++) win[j] = wblur(hb + j);

#pragma unroll
    for (int i = 0; i < HSEG; i++) {
        win[KK - 1] = wblur(hb + i + (KK - 1));

        float2 acc0 = make_float2(0.f, 0.f);
        float2 acc1 = make_float2(0.f, 0.f);
#pragma unroll
        for (int j = 0; j < KK; j++) {
            const float2 gj = make_float2(gw.g[j], gw.g[j]);
            acc0 = ffma2(gj, make_float2(win[j].x, win[j].y), acc0);
            acc1 = ffma2(gj, make_float2(win[j].z, win[j].w), acc1);
        }
        *(float4*)(dst + i * NN) = make_float4(acc0.x, acc0.y, acc1.x, acc1.y);

#pragma unroll
        for (int j = 0; j < KK - 1; j++) win[j] = win[j + 1];
    }
}

// ---------------- Kernel 2: conv along D, float2 per thread ----------------
// threadIdx.x = 0..95 spans W in float2 (coalesced 256 B per warp-load).
// 13-deep float2 register window (26 regs) -> ~7 CTAs/SM, ~42 warps/SM.
// 4 segments of 48 along d. Strides in float2 units.
__global__ void conv_axis_kernel(const float2* __restrict__ in, float2* __restrict__ out,
                                 GW gw, int cnt_lo, int s_lo, int s_hi, int stride) {
    const int o = blockIdx.y * blockDim.y + threadIdx.y;   // c*192 + h, < 576
    const int base = (o / cnt_lo) * s_hi + (o % cnt_lo) * s_lo;
    const float2* pin = in + base + threadIdx.x;
    float2* pout = out + base + threadIdx.x;

    const int p0 = blockIdx.x * 48;

    float2 win[KK];
    const float2 z2 = make_float2(0.f, 0.f);

#pragma unroll
    for (int j = 0; j < KK - 1; j++) {
        int q = p0 - RR + j;
        float2 v = z2;
        if (q >= 0 && q < NN) v = pin[q * stride];
        win[j] = v;
    }

#pragma unroll
    for (int i = 0; i < 48; i++) {
        const int p = p0 + i;
        const int q = p + RR;
        float2 v = z2;
        if (q < NN) v = pin[q * stride];
        win[KK - 1] = v;

        float2 acc = z2;
#pragma unroll
        for (int j = 0; j < KK; j++) {
            const float2 gj = make_float2(gw.g[j], gw.g[j]);
            acc = ffma2(gj, win[j], acc);
        }
        pout[p * stride] = acc;

#pragma unroll
        for (int j = 0; j < KK - 1; j++) win[j] = win[j + 1];
    }
}

extern "C" void kernel_launch(void* const* d_in, const int* in_sizes, int n_in,
                              void* d_out, int out_size) {
    const float* x = (const float*)d_in[0];   // (1,3,192,192,192) fp32
    float* out = (float*)d_out;

    void* pA = nullptr;
    cudaGetSymbolAddress(&pA, g_tmpA);
    float* tA = (float*)pA;

    // Host-side weights (double precision, normalized Gaussian, xi=2).
    GW gw;
    {
        double v[KK], s = 0.0;
        for (int j = 0; j < KK; j++) {
            double dd = (double)(j - RR);
            v[j] = exp(-dd * dd / 8.0);
            s += v[j];
        }
        for (int j = 0; j < KK; j++) gw.g[j] = (float)(v[j] / s);
    }

    // Fused W+H blur: x -> tA. 4608 CTAs of 96 threads.
    conv_wh_kernel<<<dim3(NN / WT, NN, 6), 96>>>(x, tA, gw);

    // D pass: tA -> out. float2 lanes: W = 96 float2. 4 seg x (576/2) blocks.
    conv_axis_kernel<<<dim3(4, 576 / 2), dim3(96, 2)>>>(
        (const float2*)tA, (float2*)out, gw,
        /*cnt_lo=*/NN, /*s_lo=*/NN / 2, /*s_hi=*/VOL / 2, /*stride=*/PLANE / 2);
}

// round 13
// speedup vs baseline: 2.0410x; 1.0307x over previous
#include <cuda_runtime.h>
#include <math.h>

// Depthwise 3D Gaussian blur (xi=2, K=13, pad=6) on (1,3,192,192,192) fp32.
// R12: WH kernel's W-blur switched to packed fma.rn.f32x2 (26 FFMA2 + 14
//      alu-MOV pack vs 52 scalar FFMA) -> FMA-pipe inst/thread 1560 -> 936.
//      D pass unchanged (R11 float2 config, 30.6us measured).

#define NN 192
#define RR 6
#define KK 13

#define WT   48     // w-tile (12 float4)
#define HT   96     // h outputs per CTA
#define RAWR 108    // raw rows incl +-6 h halo
#define RSTR 60     // raw row stride in floats (48 + 12 w halo)
#define HSEG 12     // h outputs per thread (8 h-groups)

constexpr int PLANE = NN * NN;          // 36864
constexpr int VOL   = NN * NN * NN;     // 7077888
constexpr long TOTAL = 3L * VOL;

// Scratch (allocation-free rule): one 85 MB temp.
__device__ __align__(16) float g_tmpA[TOTAL];

struct GW { float g[KK]; };

// Packed fp32x2 FMA (Blackwell f32x2 pipe).
__device__ __forceinline__ float2 ffma2(float2 a, float2 b, float2 c) {
    float2 r;
    asm("fma.rn.f32x2 %0, %1, %2, %3;"
        : "=l"(reinterpret_cast<unsigned long long&>(r))
        : "l"(reinterpret_cast<unsigned long long&>(a)),
          "l"(reinterpret_cast<unsigned long long&>(b)),
          "l"(reinterpret_cast<unsigned long long&>(c)));
    return r;
}

// ---------------- Kernel 1: fused W + H blur ------------------------------
// grid = (4 wchunks, 192 d, 3c x 2 hchunks), block = 96 threads (12 tw x 8 hg).
// Raw tile in smem; W-blur per row in packed f32x2, 13-deep register window
// along h. smem 25.9 KB -> 8 CTAs/SM, 24 warps/SM.
__global__ __launch_bounds__(96) void conv_wh_kernel(const float* __restrict__ in,
                                                     float* __restrict__ out, GW gw) {
    __shared__ __align__(16) float raw[RAWR * RSTR];    // 25,920 B

    const int c  = blockIdx.z >> 1;
    const int hc = blockIdx.z & 1;
    const int d  = blockIdx.y;
    const int w0 = blockIdx.x * WT;
    const int h0 = hc * HT;
    const int tid = threadIdx.x;

    const float* src = in + (c * NN + d) * PLANE;

    // ---- load raw tile: rows h0-6..h0+101, cols w0-6..w0+53 (zeros outside)
    for (int idx = tid; idx < RAWR * 30; idx += 96) {
        const int h = idx / 30;
        const int k = idx - h * 30;
        const int gh = h0 + h - RR;
        const int gwp = w0 - RR + 2 * k;
        float2 v = make_float2(0.f, 0.f);
        if ((unsigned)gh < NN && (unsigned)gwp < NN)
            v = *(const float2*)(src + gh * NN + gwp);
        *(float2*)(raw + h * RSTR + 2 * k) = v;
    }
    __syncthreads();

    const int tw = tid % 12;        // float4 slot in w
    const int hg = tid / 12;        // 0..7
    const int hb = hg * HSEG;       // local output row base

    float* dst = out + (c * NN + d) * PLANE + (h0 + hb) * NN + w0 + 4 * tw;

    // W-blur of local raw row r at float4 slot tw, packed f32x2.
    // Window rr[0..15]; o0/o1 from pairs p[j]=(rr[j],rr[j+1]) j=0..12,
    // o2/o3 from p[j+2]. Even pairs are LDS.128 halves (free); odd pairs
    // packed via alu MOVs that hide under the FMA stream.
    auto wblur = [&](int r) -> float4 {
        const float* rp = raw + r * RSTR + 4 * tw;
        const float4 x0 = *(const float4*)(rp);
        const float4 x1 = *(const float4*)(rp + 4);
        const float4 x2 = *(const float4*)(rp + 8);
        const float4 x3 = *(const float4*)(rp + 12);
        // even pairs e[k] = p[2k], k=0..7
        const float2 e0 = make_float2(x0.x, x0.y), e1 = make_float2(x0.z, x0.w);
        const float2 e2 = make_float2(x1.x, x1.y), e3 = make_float2(x1.z, x1.w);
        const float2 e4 = make_float2(x2.x, x2.y), e5 = make_float2(x2.z, x2.w);
        const float2 e6 = make_float2(x3.x, x3.y), e7 = make_float2(x3.z, x3.w);
        // odd pairs o[k] = p[2k+1] = (e[k].y, e[k+1].x), k=0..6
        const float2 p1  = make_float2(e0.y, e1.x);
        const float2 p3  = make_float2(e1.y, e2.x);
        const float2 p5  = make_float2(e2.y, e3.x);
        const float2 p7  = make_float2(e3.y, e4.x);
        const float2 p9  = make_float2(e4.y, e5.x);
        const float2 p11 = make_float2(e5.y, e6.x);
        const float2 p13 = make_float2(e6.y, e7.x);

        const float2 p[15] = {e0, p1, e1, p3, e2, p5, e3, p7,
                              e4, p9, e5, p11, e6, p13, e7};

        float2 a01 = make_float2(0.f, 0.f);
        float2 a23 = make_float2(0.f, 0.f);
#pragma unroll
        for (int j = 0; j < KK; j++) {
            const float2 gj = make_float2(gw.g[j], gw.g[j]);
            a01 = ffma2(gj, p[j],     a01);
            a23 = ffma2(gj, p[j + 2], a23);
        }
        return make_float4(a01.x, a01.y, a23.x, a23.y);
    };

    // 13-deep sliding window of W-blurred rows.
    float4 win[KK];
#pragma unroll
    for (int j = 0; j < KK - 1; j++) win[j] = wblur(hb + j);

#pragma unroll
    for (int i = 0; i < HSEG; i++) {
        win[KK - 1] = wblur(hb + i + (KK - 1));

        float2 acc0 = make_float2(0.f, 0.f);
        float2 acc1 = make_float2(0.f, 0.f);
#pragma unroll
        for (int j = 0; j < KK; j++) {
            const float2 gj = make_float2(gw.g[j], gw.g[j]);
            acc0 = ffma2(gj, make_float2(win[j].x, win[j].y), acc0);
            acc1 = ffma2(gj, make_float2(win[j].z, win[j].w), acc1);
        }
        *(float4*)(dst + i * NN) = make_float4(acc0.x, acc0.y, acc1.x, acc1.y);

#pragma unroll
        for (int j = 0; j < KK - 1; j++) win[j] = win[j + 1];
    }
}

// ---------------- Kernel 2: conv along D, float2 per thread (R11) ----------
__global__ void conv_axis_kernel(const float2* __restrict__ in, float2* __restrict__ out,
                                 GW gw, int cnt_lo, int s_lo, int s_hi, int stride) {
    const int o = blockIdx.y * blockDim.y + threadIdx.y;   // c*192 + h, < 576
    const int base = (o / cnt_lo) * s_hi + (o % cnt_lo) * s_lo;
    const float2* pin = in + base + threadIdx.x;
    float2* pout = out + base + threadIdx.x;

    const int p0 = blockIdx.x * 48;

    float2 win[KK];
    const float2 z2 = make_float2(0.f, 0.f);

#pragma unroll
    for (int j = 0; j < KK - 1; j++) {
        int q = p0 - RR + j;
        float2 v = z2;
        if (q >= 0 && q < NN) v = pin[q * stride];
        win[j] = v;
    }

#pragma unroll
    for (int i = 0; i < 48; i++) {
        const int p = p0 + i;
        const int q = p + RR;
        float2 v = z2;
        if (q < NN) v = pin[q * stride];
        win[KK - 1] = v;

        float2 acc = z2;
#pragma unroll
        for (int j = 0; j < KK; j++) {
            const float2 gj = make_float2(gw.g[j], gw.g[j]);
            acc = ffma2(gj, win[j], acc);
        }
        pout[p * stride] = acc;

#pragma unroll
        for (int j = 0; j < KK - 1; j++) win[j] = win[j + 1];
    }
}

extern "C" void kernel_launch(void* const* d_in, const int* in_sizes, int n_in,
                              void* d_out, int out_size) {
    const float* x = (const float*)d_in[0];   // (1,3,192,192,192) fp32
    float* out = (float*)d_out;

    void* pA = nullptr;
    cudaGetSymbolAddress(&pA, g_tmpA);
    float* tA = (float*)pA;

    // Host-side weights (double precision, normalized Gaussian, xi=2).
    GW gw;
    {
        double v[KK], s = 0.0;
        for (int j = 0; j < KK; j++) {
            double dd = (double)(j - RR);
            v[j] = exp(-dd * dd / 8.0);
            s += v[j];
        }
        for (int j = 0; j < KK; j++) gw.g[j] = (float)(v[j] / s);
    }

    // Fused W+H blur: x -> tA. 4608 CTAs of 96 threads.
    conv_wh_kernel<<<dim3(NN / WT, NN, 6), 96>>>(x, tA, gw);

    // D pass: tA -> out. float2 lanes: W = 96 float2. 4 seg x (576/2) blocks.
    conv_axis_kernel<<<dim3(4, 576 / 2), dim3(96, 2)>>>(
        (const float2*)tA, (float2*)out, gw,
        /*cnt_lo=*/NN, /*s_lo=*/NN / 2, /*s_hi=*/VOL / 2, /*stride=*/PLANE / 2);
}

// round 14
// speedup vs baseline: 2.2368x; 1.0960x over previous
#include <cuda_runtime.h>
#include <math.h>

// Depthwise 3D Gaussian blur (xi=2, K=13, pad=6) on (1,3,192,192,192) fp32.
// R13: WH tile-load loop made compile-time (34 fully-unrolled independent
//      LDGs -> MLP ~34, latency hidden); smem padded for overshoot writes.
//      wblur = R12 packed f32x2; D pass = R11 float2 config (29.9us).

#define NN 192
#define RR 6
#define KK 13

#define WT   48     // w-tile (12 float4)
#define HT   96     // h outputs per CTA
#define RAWR 108    // raw rows incl +-6 h halo
#define RSTR 60     // raw row stride in floats (48 + 12 w halo)
#define HSEG 12     // h outputs per thread (8 h-groups)
#define LDIT 34     // ceil(RAWR*30 / 96) fixed trip count

constexpr int PLANE = NN * NN;          // 36864
constexpr int VOL   = NN * NN * NN;     // 7077888
constexpr long TOTAL = 3L * VOL;

// Scratch (allocation-free rule): one 85 MB temp.
__device__ __align__(16) float g_tmpA[TOTAL];

struct GW { float g[KK]; };

// Packed fp32x2 FMA (Blackwell f32x2 pipe).
__device__ __forceinline__ float2 ffma2(float2 a, float2 b, float2 c) {
    float2 r;
    asm("fma.rn.f32x2 %0, %1, %2, %3;"
        : "=l"(reinterpret_cast<unsigned long long&>(r))
        : "l"(reinterpret_cast<unsigned long long&>(a)),
          "l"(reinterpret_cast<unsigned long long&>(b)),
          "l"(reinterpret_cast<unsigned long long&>(c)));
    return r;
}

// ---------------- Kernel 1: fused W + H blur ------------------------------
// grid = (4 wchunks, 192 d, 3c x 2 hchunks), block = 96 threads (12 tw x 8 hg).
__global__ __launch_bounds__(96) void conv_wh_kernel(const float* __restrict__ in,
                                                     float* __restrict__ out, GW gw) {
    // +64 floats pad: unrolled loader's tail writes (idx in [3240,3263]) land here.
    __shared__ __align__(16) float raw[RAWR * RSTR + 64];   // 26,176 B

    const int c  = blockIdx.z >> 1;
    const int hc = blockIdx.z & 1;
    const int d  = blockIdx.y;
    const int w0 = blockIdx.x * WT;
    const int h0 = hc * HT;
    const int tid = threadIdx.x;

    const float* src = in + (c * NN + d) * PLANE;

    // ---- load raw tile: rows h0-6..h0+101, cols w0-6..w0+53 (zeros outside)
    // Fixed 34-iteration unroll: 34 independent predicated LDG.64s per thread
    // front-batched by ptxas -> MLP ~34, DRAM latency fully overlapped.
#pragma unroll
    for (int i = 0; i < LDIT; i++) {
        const int idx = tid + i * 96;          // < 3264
        const int h = idx / 30;                // mul-shift, no cross-iter dep
        const int k = idx - h * 30;
        const int gh = h0 + h - RR;
        const int gwp = w0 - RR + 2 * k;
        float2 v = make_float2(0.f, 0.f);
        if ((unsigned)gh < NN && (unsigned)gwp < NN)
            v = *(const float2*)(src + gh * NN + gwp);
        *(float2*)(raw + h * RSTR + 2 * k) = v;
    }
    __syncthreads();

    const int tw = tid % 12;        // float4 slot in w
    const int hg = tid / 12;        // 0..7
    const int hb = hg * HSEG;       // local output row base

    float* dst = out + (c * NN + d) * PLANE + (h0 + hb) * NN + w0 + 4 * tw;

    // W-blur of local raw row r at float4 slot tw, packed f32x2 (R12).
    auto wblur = [&](int r) -> float4 {
        const float* rp = raw + r * RSTR + 4 * tw;
        const float4 x0 = *(const float4*)(rp);
        const float4 x1 = *(const float4*)(rp + 4);
        const float4 x2 = *(const float4*)(rp + 8);
        const float4 x3 = *(const float4*)(rp + 12);
        const float2 e0 = make_float2(x0.x, x0.y), e1 = make_float2(x0.z, x0.w);
        const float2 e2 = make_float2(x1.x, x1.y), e3 = make_float2(x1.z, x1.w);
        const float2 e4 = make_float2(x2.x, x2.y), e5 = make_float2(x2.z, x2.w);
        const float2 e6 = make_float2(x3.x, x3.y), e7 = make_float2(x3.z, x3.w);
        const float2 p1  = make_float2(e0.y, e1.x);
        const float2 p3  = make_float2(e1.y, e2.x);
        const float2 p5  = make_float2(e2.y, e3.x);
        const float2 p7  = make_float2(e3.y, e4.x);
        const float2 p9  = make_float2(e4.y, e5.x);
        const float2 p11 = make_float2(e5.y, e6.x);
        const float2 p13 = make_float2(e6.y, e7.x);

        const float2 p[15] = {e0, p1, e1, p3, e2, p5, e3, p7,
                              e4, p9, e5, p11, e6, p13, e7};

        float2 a01 = make_float2(0.f, 0.f);
        float2 a23 = make_float2(0.f, 0.f);
#pragma unroll
        for (int j = 0; j < KK; j++) {
            const float2 gj = make_float2(gw.g[j], gw.g[j]);
            a01 = ffma2(gj, p[j],     a01);
            a23 = ffma2(gj, p[j + 2], a23);
        }
        return make_float4(a01.x, a01.y, a23.x, a23.y);
    };

    // 13-deep sliding window of W-blurred rows.
    float4 win[KK];
#pragma unroll
    for (int j = 0; j < KK - 1; j++) win[j] = wblur(hb + j);

#pragma unroll
    for (int i = 0; i < HSEG; i++) {
        win[KK - 1] = wblur(hb + i + (KK - 1));

        float2 acc0 = make_float2(0.f, 0.f);
        float2 acc1 = make_float2(0.f, 0.f);
#pragma unroll
        for (int j = 0; j < KK; j++) {
            const float2 gj = make_float2(gw.g[j], gw.g[j]);
            acc0 = ffma2(gj, make_float2(win[j].x, win[j].y), acc0);
            acc1 = ffma2(gj, make_float2(win[j].z, win[j].w), acc1);
        }
        *(float4*)(dst + i * NN) = make_float4(acc0.x, acc0.y, acc1.x, acc1.y);

#pragma unroll
        for (int j = 0; j < KK - 1; j++) win[j] = win[j + 1];
    }
}

// ---------------- Kernel 2: conv along D, float2 per thread (R11) ----------
__global__ void conv_axis_kernel(const float2* __restrict__ in, float2* __restrict__ out,
                                 GW gw, int cnt_lo, int s_lo, int s_hi, int stride) {
    const int o = blockIdx.y * blockDim.y + threadIdx.y;   // c*192 + h, < 576
    const int base = (o / cnt_lo) * s_hi + (o % cnt_lo) * s_lo;
    const float2* pin = in + base + threadIdx.x;
    float2* pout = out + base + threadIdx.x;

    const int p0 = blockIdx.x * 48;

    float2 win[KK];
    const float2 z2 = make_float2(0.f, 0.f);

#pragma unroll
    for (int j = 0; j < KK - 1; j++) {
        int q = p0 - RR + j;
        float2 v = z2;
        if (q >= 0 && q < NN) v = pin[q * stride];
        win[j] = v;
    }

#pragma unroll
    for (int i = 0; i < 48; i++) {
        const int p = p0 + i;
        const int q = p + RR;
        float2 v = z2;
        if (q < NN) v = pin[q * stride];
        win[KK - 1] = v;

        float2 acc = z2;
#pragma unroll
        for (int j = 0; j < KK; j++) {
            const float2 gj = make_float2(gw.g[j], gw.g[j]);
            acc = ffma2(gj, win[j], acc);
        }
        pout[p * stride] = acc;

#pragma unroll
        for (int j = 0; j < KK - 1; j++) win[j] = win[j + 1];
    }
}

extern "C" void kernel_launch(void* const* d_in, const int* in_sizes, int n_in,
                              void* d_out, int out_size) {
    const float* x = (const float*)d_in[0];   // (1,3,192,192,192) fp32
    float* out = (float*)d_out;

    void* pA = nullptr;
    cudaGetSymbolAddress(&pA, g_tmpA);
    float* tA = (float*)pA;

    // Host-side weights (double precision, normalized Gaussian, xi=2).
    GW gw;
    {
        double v[KK], s = 0.0;
        for (int j = 0; j < KK; j++) {
            double dd = (double)(j - RR);
            v[j] = exp(-dd * dd / 8.0);
            s += v[j];
        }
        for (int j = 0; j < KK; j++) gw.g[j] = (float)(v[j] / s);
    }

    // Fused W+H blur: x -> tA. 4608 CTAs of 96 threads.
    conv_wh_kernel<<<dim3(NN / WT, NN, 6), 96>>>(x, tA, gw);

    // D pass: tA -> out. float2 lanes: W = 96 float2. 4 seg x (576/2) blocks.
    conv_axis_kernel<<<dim3(4, 576 / 2), dim3(96, 2)>>>(
        (const float2*)tA, (float2*)out, gw,
        /*cnt_lo=*/NN, /*s_lo=*/NN / 2, /*s_hi=*/VOL / 2, /*stride=*/PLANE / 2);
}

// round 15
// speedup vs baseline: 2.4388x; 1.0903x over previous
#include <cuda_runtime.h>
#include <math.h>

// Depthwise 3D Gaussian blur (xi=2, K=13, pad=6) on (1,3,192,192,192) fp32.
// R14: WH tile widened to 96x96 (halo amp 1.41 -> 1.27), 192-thread CTAs,
//      46.7 KB smem -> 4 CTAs/SM (24 warps, unchanged). Unrolled MLP loader
//      and packed-f32x2 wblur retained. D pass = R11 config (30.5us).

#define NN 192
#define RR 6
#define KK 13

#define WT   96     // w-tile (24 float4)
#define HT   96     // h outputs per CTA
#define RAWR 108    // raw rows incl +-6 h halo
#define RSTR 108    // raw row stride in floats (96 + 12 w halo)
#define HSEG 12     // h outputs per thread (8 h-groups)
#define LD2  54     // float2 per row
#define LDIT 31     // ceil(RAWR*LD2 / 192) = ceil(5832/192)

constexpr int PLANE = NN * NN;          // 36864
constexpr int VOL   = NN * NN * NN;     // 7077888
constexpr long TOTAL = 3L * VOL;

// Scratch (allocation-free rule): one 85 MB temp.
__device__ __align__(16) float g_tmpA[TOTAL];

struct GW { float g[KK]; };

// Packed fp32x2 FMA (Blackwell f32x2 pipe).
__device__ __forceinline__ float2 ffma2(float2 a, float2 b, float2 c) {
    float2 r;
    asm("fma.rn.f32x2 %0, %1, %2, %3;"
        : "=l"(reinterpret_cast<unsigned long long&>(r))
        : "l"(reinterpret_cast<unsigned long long&>(a)),
          "l"(reinterpret_cast<unsigned long long&>(b)),
          "l"(reinterpret_cast<unsigned long long&>(c)));
    return r;
}

// ---------------- Kernel 1: fused W + H blur ------------------------------
// grid = (2 wchunks, 192 d, 3c x 2 hchunks), block = 192 (24 tw x 8 hg).
__global__ __launch_bounds__(192) void conv_wh_kernel(const float* __restrict__ in,
                                                      float* __restrict__ out, GW gw) {
    // +320 floats pad: unrolled loader tail (idx 5832..5951 -> h up to 110).
    __shared__ __align__(16) float raw[RAWR * RSTR + 320];   // 47,936 B

    const int c  = blockIdx.z >> 1;
    const int hc = blockIdx.z & 1;
    const int d  = blockIdx.y;
    const int w0 = blockIdx.x * WT;
    const int h0 = hc * HT;
    const int tid = threadIdx.x;

    const float* src = in + (c * NN + d) * PLANE;

    // ---- load raw tile: rows h0-6..h0+101, cols w0-6..w0+101 (zeros outside)
    // Fixed 31-iteration unroll: independent predicated LDG.64s, MLP ~31.
#pragma unroll
    for (int i = 0; i < LDIT; i++) {
        const int idx = tid + i * 192;         // < 5952
        const int h = idx / LD2;
        const int k = idx - h * LD2;
        const int gh = h0 + h - RR;
        const int gwp = w0 - RR + 2 * k;
        float2 v = make_float2(0.f, 0.f);
        if ((unsigned)gh < NN && (unsigned)gwp < NN)
            v = *(const float2*)(src + gh * NN + gwp);
        *(float2*)(raw + h * RSTR + 2 * k) = v;
    }
    __syncthreads();

    const int tw = tid % 24;        // float4 slot in w (0..23)
    const int hg = tid / 24;        // 0..7
    const int hb = hg * HSEG;       // local output row base

    float* dst = out + (c * NN + d) * PLANE + (h0 + hb) * NN + w0 + 4 * tw;

    // W-blur of local raw row r at float4 slot tw, packed f32x2.
    auto wblur = [&](int r) -> float4 {
        const float* rp = raw + r * RSTR + 4 * tw;
        const float4 x0 = *(const float4*)(rp);
        const float4 x1 = *(const float4*)(rp + 4);
        const float4 x2 = *(const float4*)(rp + 8);
        const float4 x3 = *(const float4*)(rp + 12);
        const float2 e0 = make_float2(x0.x, x0.y), e1 = make_float2(x0.z, x0.w);
        const float2 e2 = make_float2(x1.x, x1.y), e3 = make_float2(x1.z, x1.w);
        const float2 e4 = make_float2(x2.x, x2.y), e5 = make_float2(x2.z, x2.w);
        const float2 e6 = make_float2(x3.x, x3.y), e7 = make_float2(x3.z, x3.w);
        const float2 p1  = make_float2(e0.y, e1.x);
        const float2 p3  = make_float2(e1.y, e2.x);
        const float2 p5  = make_float2(e2.y, e3.x);
        const float2 p7  = make_float2(e3.y, e4.x);
        const float2 p9  = make_float2(e4.y, e5.x);
        const float2 p11 = make_float2(e5.y, e6.x);
        const float2 p13 = make_float2(e6.y, e7.x);

        const float2 p[15] = {e0, p1, e1, p3, e2, p5, e3, p7,
                              e4, p9, e5, p11, e6, p13, e7};

        float2 a01 = make_float2(0.f, 0.f);
        float2 a23 = make_float2(0.f, 0.f);
#pragma unroll
        for (int j = 0; j < KK; j++) {
            const float2 gj = make_float2(gw.g[j], gw.g[j]);
            a01 = ffma2(gj, p[j],     a01);
            a23 = ffma2(gj, p[j + 2], a23);
        }
        return make_float4(a01.x, a01.y, a23.x, a23.y);
    };

    // 13-deep sliding window of W-blurred rows (raw rows hb..hb+23 <= 107).
    float4 win[KK];
#pragma unroll
    for (int j = 0; j < KK - 1; j++) win[j] = wblur(hb + j);

#pragma unroll
    for (int i = 0; i < HSEG; i++) {
        win[KK - 1] = wblur(hb + i + (KK - 1));

        float2 acc0 = make_float2(0.f, 0.f);
        float2 acc1 = make_float2(0.f, 0.f);
#pragma unroll
        for (int j = 0; j < KK; j++) {
            const float2 gj = make_float2(gw.g[j], gw.g[j]);
            acc0 = ffma2(gj, make_float2(win[j].x, win[j].y), acc0);
            acc1 = ffma2(gj, make_float2(win[j].z, win[j].w), acc1);
        }
        *(float4*)(dst + i * NN) = make_float4(acc0.x, acc0.y, acc1.x, acc1.y);

#pragma unroll
        for (int j = 0; j < KK - 1; j++) win[j] = win[j + 1];
    }
}

// ---------------- Kernel 2: conv along D, float2 per thread (R11) ----------
__global__ void conv_axis_kernel(const float2* __restrict__ in, float2* __restrict__ out,
                                 GW gw, int cnt_lo, int s_lo, int s_hi, int stride) {
    const int o = blockIdx.y * blockDim.y + threadIdx.y;   // c*192 + h, < 576
    const int base = (o / cnt_lo) * s_hi + (o % cnt_lo) * s_lo;
    const float2* pin = in + base + threadIdx.x;
    float2* pout = out + base + threadIdx.x;

    const int p0 = blockIdx.x * 48;

    float2 win[KK];
    const float2 z2 = make_float2(0.f, 0.f);

#pragma unroll
    for (int j = 0; j < KK - 1; j++) {
        int q = p0 - RR + j;
        float2 v = z2;
        if (q >= 0 && q < NN) v = pin[q * stride];
        win[j] = v;
    }

#pragma unroll
    for (int i = 0; i < 48; i++) {
        const int p = p0 + i;
        const int q = p + RR;
        float2 v = z2;
        if (q < NN) v = pin[q * stride];
        win[KK - 1] = v;

        float2 acc = z2;
#pragma unroll
        for (int j = 0; j < KK; j++) {
            const float2 gj = make_float2(gw.g[j], gw.g[j]);
            acc = ffma2(gj, win[j], acc);
        }
        pout[p * stride] = acc;

#pragma unroll
        for (int j = 0; j < KK - 1; j++) win[j] = win[j + 1];
    }
}

extern "C" void kernel_launch(void* const* d_in, const int* in_sizes, int n_in,
                              void* d_out, int out_size) {
    const float* x = (const float*)d_in[0];   // (1,3,192,192,192) fp32
    float* out = (float*)d_out;

    void* pA = nullptr;
    cudaGetSymbolAddress(&pA, g_tmpA);
    float* tA = (float*)pA;

    // Host-side weights (double precision, normalized Gaussian, xi=2).
    GW gw;
    {
        double v[KK], s = 0.0;
        for (int j = 0; j < KK; j++) {
            double dd = (double)(j - RR);
            v[j] = exp(-dd * dd / 8.0);
            s += v[j];
        }
        for (int j = 0; j < KK; j++) gw.g[j] = (float)(v[j] / s);
    }

    // Fused W+H blur: x -> tA. 2304 CTAs of 192 threads.
    conv_wh_kernel<<<dim3(NN / WT, NN, 6), 192>>>(x, tA, gw);

    // D pass: tA -> out. float2 lanes: W = 96 float2. 4 seg x (576/2) blocks.
    conv_axis_kernel<<<dim3(4, 576 / 2), dim3(96, 2)>>>(
        (const float2*)tA, (float2*)out, gw,
        /*cnt_lo=*/NN, /*s_lo=*/NN / 2, /*s_hi=*/VOL / 2, /*stride=*/PLANE / 2);
}

// round 16
// speedup vs baseline: 2.6369x; 1.0812x over previous
#include <cuda_runtime.h>
#include <math.h>

// Depthwise 3D Gaussian blur (xi=2, K=13, pad=6) on (1,3,192,192,192) fp32.
// R15: WH tile loader switched to cp.async (zfill, no register staging);
//      D pass switched to float1-per-thread (13-reg window -> ~2x occupancy).

#define NN 192
#define RR 6
#define KK 13

#define WT   96     // w-tile (24 float4)
#define HT   96     // h outputs per CTA
#define RAWR 108    // raw rows incl +-6 h halo
#define RSTR 108    // raw row stride in floats (96 + 12 w halo)
#define HSEG 12     // h outputs per thread (8 h-groups)
#define LD2  54     // float2 per row
#define LDIT 31     // ceil(RAWR*LD2 / 192)

constexpr int PLANE = NN * NN;          // 36864
constexpr int VOL   = NN * NN * NN;     // 7077888
constexpr long TOTAL = 3L * VOL;

// Scratch (allocation-free rule): one 85 MB temp.
__device__ __align__(16) float g_tmpA[TOTAL];

struct GW { float g[KK]; };

// Packed fp32x2 FMA (Blackwell f32x2 pipe).
__device__ __forceinline__ float2 ffma2(float2 a, float2 b, float2 c) {
    float2 r;
    asm("fma.rn.f32x2 %0, %1, %2, %3;"
        : "=l"(reinterpret_cast<unsigned long long&>(r))
        : "l"(reinterpret_cast<unsigned long long&>(a)),
          "l"(reinterpret_cast<unsigned long long&>(b)),
          "l"(reinterpret_cast<unsigned long long&>(c)));
    return r;
}

// 8-byte cp.async with runtime src-size (0 -> zero-fill, no global read).
__device__ __forceinline__ void cpasync8(unsigned saddr, const void* g, int sz) {
    asm volatile("cp.async.ca.shared.global [%0], [%1], 8, %2;"
                 :: "r"(saddr), "l"(g), "r"(sz) : "memory");
}

// ---------------- Kernel 1: fused W + H blur ------------------------------
// grid = (2 wchunks, 192 d, 3c x 2 hchunks), block = 192 (24 tw x 8 hg).
__global__ __launch_bounds__(192) void conv_wh_kernel(const float* __restrict__ in,
                                                      float* __restrict__ out, GW gw) {
    // +320 floats pad: unrolled loader tail (idx 5832..5951 -> h up to 110).
    __shared__ __align__(16) float raw[RAWR * RSTR + 320];   // 47,936 B

    const int c  = blockIdx.z >> 1;
    const int hc = blockIdx.z & 1;
    const int d  = blockIdx.y;
    const int w0 = blockIdx.x * WT;
    const int h0 = hc * HT;
    const int tid = threadIdx.x;

    const float* src = in + (c * NN + d) * PLANE;
    const unsigned sbase = (unsigned)__cvta_generic_to_shared(raw);

    // ---- load raw tile via cp.async: rows h0-6..h0+101, cols w0-6..w0+101,
    // zero-fill outside. 31 fixed iterations, no destination registers.
#pragma unroll
    for (int i = 0; i < LDIT; i++) {
        const int idx = tid + i * 192;         // < 5952
        const int h = idx / LD2;
        const int k = idx - h * LD2;
        const int gh = h0 + h - RR;
        const int gwp = w0 - RR + 2 * k;
        const bool ok = ((unsigned)gh < NN) && ((unsigned)gwp < NN);
        const float* g = src + (ok ? (gh * NN + gwp) : 0);
        cpasync8(sbase + (unsigned)(h * RSTR + 2 * k) * 4u, g, ok ? 8 : 0);
    }
    asm volatile("cp.async.commit_group;" ::: "memory");
    asm volatile("cp.async.wait_group 0;" ::: "memory");
    __syncthreads();

    const int tw = tid % 24;        // float4 slot in w (0..23)
    const int hg = tid / 24;        // 0..7
    const int hb = hg * HSEG;       // local output row base

    float* dst = out + (c * NN + d) * PLANE + (h0 + hb) * NN + w0 + 4 * tw;

    // W-blur of local raw row r at float4 slot tw, packed f32x2.
    auto wblur = [&](int r) -> float4 {
        const float* rp = raw + r * RSTR + 4 * tw;
        const float4 x0 = *(const float4*)(rp);
        const float4 x1 = *(const float4*)(rp + 4);
        const float4 x2 = *(const float4*)(rp + 8);
        const float4 x3 = *(const float4*)(rp + 12);
        const float2 e0 = make_float2(x0.x, x0.y), e1 = make_float2(x0.z, x0.w);
        const float2 e2 = make_float2(x1.x, x1.y), e3 = make_float2(x1.z, x1.w);
        const float2 e4 = make_float2(x2.x, x2.y), e5 = make_float2(x2.z, x2.w);
        const float2 e6 = make_float2(x3.x, x3.y), e7 = make_float2(x3.z, x3.w);
        const float2 p1  = make_float2(e0.y, e1.x);
        const float2 p3  = make_float2(e1.y, e2.x);
        const float2 p5  = make_float2(e2.y, e3.x);
        const float2 p7  = make_float2(e3.y, e4.x);
        const float2 p9  = make_float2(e4.y, e5.x);
        const float2 p11 = make_float2(e5.y, e6.x);
        const float2 p13 = make_float2(e6.y, e7.x);

        const float2 p[15] = {e0, p1, e1, p3, e2, p5, e3, p7,
                              e4, p9, e5, p11, e6, p13, e7};

        float2 a01 = make_float2(0.f, 0.f);
        float2 a23 = make_float2(0.f, 0.f);
#pragma unroll
        for (int j = 0; j < KK; j++) {
            const float2 gj = make_float2(gw.g[j], gw.g[j]);
            a01 = ffma2(gj, p[j],     a01);
            a23 = ffma2(gj, p[j + 2], a23);
        }
        return make_float4(a01.x, a01.y, a23.x, a23.y);
    };

    // 13-deep sliding window of W-blurred rows (raw rows hb..hb+23 <= 107).
    float4 win[KK];
#pragma unroll
    for (int j = 0; j < KK - 1; j++) win[j] = wblur(hb + j);

#pragma unroll
    for (int i = 0; i < HSEG; i++) {
        win[KK - 1] = wblur(hb + i + (KK - 1));

        float2 acc0 = make_float2(0.f, 0.f);
        float2 acc1 = make_float2(0.f, 0.f);
#pragma unroll
        for (int j = 0; j < KK; j++) {
            const float2 gj = make_float2(gw.g[j], gw.g[j]);
            acc0 = ffma2(gj, make_float2(win[j].x, win[j].y), acc0);
            acc1 = ffma2(gj, make_float2(win[j].z, win[j].w), acc1);
        }
        *(float4*)(dst + i * NN) = make_float4(acc0.x, acc0.y, acc1.x, acc1.y);

#pragma unroll
        for (int j = 0; j < KK - 1; j++) win[j] = win[j + 1];
    }
}

// ---------------- Kernel 2: conv along D, float1 per thread ----------------
// threadIdx.x = 0..191 spans full W (warp load = 128 B coalesced).
// 13-reg window -> ~30 regs/thread -> occupancy toward 60+ warps/SM.
// 4 segments of 48 along d. grid (4, 576) = 2304 CTAs.
__global__ __launch_bounds__(192) void conv_axis_kernel(const float* __restrict__ in,
                                                        float* __restrict__ out, GW gw) {
    const int o = blockIdx.y;                  // c*192 + h, < 576
    const int base = (o / NN) * VOL + (o % NN) * NN;
    const float* pin = in + base + threadIdx.x;
    float* pout = out + base + threadIdx.x;

    const int p0 = blockIdx.x * 48;

    float win[KK];

#pragma unroll
    for (int j = 0; j < KK - 1; j++) {
        const int q = p0 - RR + j;
        float v = 0.f;
        if (q >= 0 && q < NN) v = pin[q * PLANE];
        win[j] = v;
    }

#pragma unroll
    for (int i = 0; i < 48; i++) {
        const int p = p0 + i;
        const int q = p + RR;
        float v = 0.f;
        if (q < NN) v = pin[q * PLANE];
        win[KK - 1] = v;

        float acc = 0.f;
#pragma unroll
        for (int j = 0; j < KK; j++) acc = fmaf(gw.g[j], win[j], acc);
        pout[p * PLANE] = acc;

#pragma unroll
        for (int j = 0; j < KK - 1; j++) win[j] = win[j + 1];
    }
}

extern "C" void kernel_launch(void* const* d_in, const int* in_sizes, int n_in,
                              void* d_out, int out_size) {
    const float* x = (const float*)d_in[0];   // (1,3,192,192,192) fp32
    float* out = (float*)d_out;

    void* pA = nullptr;
    cudaGetSymbolAddress(&pA, g_tmpA);
    float* tA = (float*)pA;

    // Host-side weights (double precision, normalized Gaussian, xi=2).
    GW gw;
    {
        double v[KK], s = 0.0;
        for (int j = 0; j < KK; j++) {
            double dd = (double)(j - RR);
            v[j] = exp(-dd * dd / 8.0);
            s += v[j];
        }
        for (int j = 0; j < KK; j++) gw.g[j] = (float)(v[j] / s);
    }

    // Fused W+H blur: x -> tA. 2304 CTAs of 192 threads.
    conv_wh_kernel<<<dim3(NN / WT, NN, 6), 192>>>(x, tA, gw);

    // D pass: tA -> out. float1 lanes across full W. grid (4, 576).
    conv_axis_kernel<<<dim3(4, 576), 192>>>(tA, out, gw);
}